// round 8
// baseline (speedup 1.0000x reference)
#include <cuda_runtime.h>
#include <cuda_fp16.h>
#include <stdint.h>

// ---------------------------------------------------------------------------
#define VOCAB 30000
#define DIM   512
#define FEAT  256
#define SEQL  128
#define NSEQ  1024
#define NCOL  3072

__device__ __align__(128) __half g_Ah[(size_t)VOCAB * DIM];
__device__ __align__(128) __half g_Bh[(size_t)NCOL * DIM];
__device__ __align__(128) __half g_proj[(size_t)VOCAB * NCOL];

// ---------------------------------------------------------------------------
static __device__ __forceinline__ uint32_t smem_u32(const void* p) {
    uint32_t a;
    asm("{ .reg .u64 t; cvta.to.shared.u64 t, %1; cvt.u32.u64 %0, t; }" : "=r"(a) : "l"(p));
    return a;
}
static __device__ __forceinline__ void cpa16(uint32_t s, const void* g) {
    asm volatile("cp.async.cg.shared.global [%0], [%1], 16;" :: "r"(s), "l"(g));
}
static __device__ __forceinline__ void cp_commit() {
    asm volatile("cp.async.commit_group;" ::: "memory");
}
template <int N> static __device__ __forceinline__ void cp_wait() {
    asm volatile("cp.async.wait_group %0;" :: "n"(N) : "memory");
}
static __device__ __forceinline__ void ldsm4(uint32_t& r0, uint32_t& r1,
                                             uint32_t& r2, uint32_t& r3, uint32_t a) {
    asm volatile("ldmatrix.sync.aligned.m8n8.x4.shared.b16 {%0,%1,%2,%3}, [%4];"
                 : "=r"(r0), "=r"(r1), "=r"(r2), "=r"(r3) : "r"(a));
}
static __device__ __forceinline__ void mma16816(float* d, const uint32_t* a,
                                                const uint32_t* b) {
    asm volatile(
        "mma.sync.aligned.m16n8k16.row.col.f32.f16.f16.f32 "
        "{%0,%1,%2,%3}, {%4,%5,%6,%7}, {%8,%9}, {%0,%1,%2,%3};"
        : "+f"(d[0]), "+f"(d[1]), "+f"(d[2]), "+f"(d[3])
        : "r"(a[0]), "r"(a[1]), "r"(a[2]), "r"(a[3]), "r"(b[0]), "r"(b[1]));
}
static __device__ __forceinline__ float2 add2(float2 a, float2 b) {
    return make_float2(a.x + b.x, a.y + b.y);
}
static __device__ __forceinline__ float2 max2(float2 a, float2 b) {
    return make_float2(fmaxf(a.x, b.x), fmaxf(a.y, b.y));
}

// ---------------------------------------------------------------------------
// Kernel 1: embed fp32 -> fp16
// ---------------------------------------------------------------------------
__global__ void convert_embed(const float* __restrict__ e) {
    size_t i = ((size_t)blockIdx.x * blockDim.x + threadIdx.x) * 8;
    if (i >= (size_t)VOCAB * DIM) return;
    float4 v0 = *reinterpret_cast<const float4*>(e + i);
    float4 v1 = *reinterpret_cast<const float4*>(e + i + 4);
    __align__(16) __half h[8];
    h[0] = __float2half_rn(v0.x); h[1] = __float2half_rn(v0.y);
    h[2] = __float2half_rn(v0.z); h[3] = __float2half_rn(v0.w);
    h[4] = __float2half_rn(v1.x); h[5] = __float2half_rn(v1.y);
    h[6] = __float2half_rn(v1.z); h[7] = __float2half_rn(v1.w);
    *reinterpret_cast<uint4*>(&g_Ah[i]) = *reinterpret_cast<uint4*>(h);
}

// ---------------------------------------------------------------------------
// Kernel 2: pack weights B[n][k], n = tap*256+f
// ---------------------------------------------------------------------------
__global__ void pack_w(const float* __restrict__ w3,
                       const float* __restrict__ w4,
                       const float* __restrict__ w5) {
    int idx = blockIdx.x * blockDim.x + threadIdx.x;
    if (idx >= NCOL * DIM) return;
    int n = idx >> 9;
    int k = idx & 511;
    int tap = n >> 8;
    int f   = n & 255;
    float v;
    if (tap < 3)      v = w3[(f * DIM + k) * 3 + tap];
    else if (tap < 7) v = w4[(f * DIM + k) * 4 + (tap - 3)];
    else              v = w5[(f * DIM + k) * 5 + (tap - 7)];
    g_Bh[idx] = __float2half_rn(v);
}

// ---------------------------------------------------------------------------
// Kernel 3: fp16 mma.sync GEMM, K=512, persistent 5-tile M-chain per CTA
//   one continuous 40-stage cp.async pipeline; epilogue overlapped by
//   in-flight loads of the next tile
// ---------------------------------------------------------------------------
#define BM 128
#define BN 256
#define BKH 64
#define STAGES 4
#define ASTG 16384
#define BSTG 32768
#define STG (ASTG + BSTG)          // 48KB / stage
#define CHAIN 5                    // m-tiles per CTA
#define NST (CHAIN * 8)            // 40 pipeline stages
#define GEMM_SMEM (STAGES * STG + 1024)

__global__ __launch_bounds__(256, 1) void gemm_f16() {
    extern __shared__ char dyn[];
    uint32_t base = (smem_u32(dyn) + 1023) & ~1023u;

    int tid  = threadIdx.x;
    int lane = tid & 31;
    int warp = tid >> 5;
    int wm = warp >> 2;
    int wn = warp & 3;
    int n0 = blockIdx.x * BN;
    int mbase = blockIdx.y * CHAIN;      // first m-tile index of this chain

    int aRow[4], aXor[4];
#pragma unroll
    for (int mt = 0; mt < 4; mt++) {
        int r = wm * 64 + mt * 16 + (lane & 15);
        aRow[mt] = r * 128;
        aXor[mt] = r & 7;
    }
    int aCb = lane >> 4;
    int bRow[4], bXor[4];
#pragma unroll
    for (int ntp = 0; ntp < 4; ntp++) {
        int r = wn * 64 + ntp * 16 + (lane & 7) + ((lane >> 4) << 3);
        bRow[ntp] = r * 128;
        bXor[ntp] = r & 7;
    }
    int bCb = (lane >> 3) & 1;

    float acc[4][8][4];
#pragma unroll
    for (int mt = 0; mt < 4; mt++)
#pragma unroll
        for (int nt = 0; nt < 8; nt++)
#pragma unroll
            for (int q = 0; q < 4; q++) acc[mt][nt][q] = 0.f;

    auto load_stage = [&](int g) {
        int m0 = (mbase + (g >> 3)) * BM;
        int k0 = (g & 7) * BKH;
        uint32_t sA = base + (g % STAGES) * STG;
        uint32_t sB = sA + ASTG;
#pragma unroll
        for (int j = 0; j < 4; j++) {
            int c = tid + 256 * j;
            int r = c >> 3, q = c & 7;
            int grow = m0 + r; if (grow >= VOCAB) grow = VOCAB - 1;
            uint32_t off = (uint32_t)(r * 128 + ((q ^ (r & 7)) << 4));
            cpa16(sA + off, g_Ah + (size_t)grow * DIM + k0 + q * 8);
        }
#pragma unroll
        for (int j = 0; j < 8; j++) {
            int c = tid + 256 * j;
            int r = c >> 3, q = c & 7;
            uint32_t off = (uint32_t)(r * 128 + ((q ^ (r & 7)) << 4));
            cpa16(sB + off, g_Bh + (size_t)(n0 + r) * DIM + k0 + q * 8);
        }
        cp_commit();
    };

    load_stage(0);
    load_stage(1);
    load_stage(2);

    for (int g = 0; g < NST; g++) {
        if (g < NST - 2)       cp_wait<2>();
        else if (g == NST - 2) cp_wait<1>();
        else                   cp_wait<0>();
        __syncthreads();       // protects buffer (g+3)%4 (read finished in iter g-1)

        if (g + 3 < NST) load_stage(g + 3);

        uint32_t sA = base + (g % STAGES) * STG;
        uint32_t sB = sA + ASTG;

        uint32_t a[2][4][4], b[2][8][2];
        auto ldA = [&](int s, int buf) {
#pragma unroll
            for (int mt = 0; mt < 4; mt++) {
                uint32_t addr = sA + aRow[mt] + ((uint32_t)((2 * s + aCb) ^ aXor[mt]) << 4);
                ldsm4(a[buf][mt][0], a[buf][mt][1], a[buf][mt][2], a[buf][mt][3], addr);
            }
        };
        auto ldB = [&](int s, int buf) {
#pragma unroll
            for (int ntp = 0; ntp < 4; ntp++) {
                uint32_t addr = sB + bRow[ntp] + ((uint32_t)((2 * s + bCb) ^ bXor[ntp]) << 4);
                ldsm4(b[buf][2 * ntp][0], b[buf][2 * ntp][1],
                      b[buf][2 * ntp + 1][0], b[buf][2 * ntp + 1][1], addr);
            }
        };

        ldA(0, 0); ldB(0, 0);
#pragma unroll
        for (int s = 0; s < 4; s++) {
            int cur = s & 1;
            if (s < 3) { ldA(s + 1, cur ^ 1); ldB(s + 1, cur ^ 1); }
#pragma unroll
            for (int mt = 0; mt < 4; mt++)
#pragma unroll
                for (int nt = 0; nt < 8; nt++)
                    mma16816(acc[mt][nt], a[cur][mt], b[cur][nt]);
        }

        if ((g & 7) == 7) {
            // ---- tile epilogue (registers only; next tile's loads in flight) ----
            int m0 = (mbase + (g >> 3)) * BM;
#pragma unroll
            for (int mt = 0; mt < 4; mt++) {
                int r0 = m0 + wm * 64 + mt * 16 + (lane >> 2);
                int r1 = r0 + 8;
                __half* p0 = g_proj + (size_t)r0 * NCOL + n0 + wn * 64 + (lane & 3) * 2;
                __half* p1 = g_proj + (size_t)r1 * NCOL + n0 + wn * 64 + (lane & 3) * 2;
                bool ok0 = r0 < VOCAB, ok1 = r1 < VOCAB;
#pragma unroll
                for (int nt = 0; nt < 8; nt++) {
                    if (ok0) *reinterpret_cast<__half2*>(p0 + nt * 8) =
                        __floats2half2_rn(acc[mt][nt][0], acc[mt][nt][1]);
                    if (ok1) *reinterpret_cast<__half2*>(p1 + nt * 8) =
                        __floats2half2_rn(acc[mt][nt][2], acc[mt][nt][3]);
                }
            }
#pragma unroll
            for (int mt = 0; mt < 4; mt++)
#pragma unroll
                for (int nt = 0; nt < 8; nt++)
#pragma unroll
                    for (int q = 0; q < 4; q++) acc[mt][nt][q] = 0.f;
        }
    }
}

// ---------------------------------------------------------------------------
// Kernel 4a: zero output (atomicMax accumulation target)
// ---------------------------------------------------------------------------
__global__ void init_out(float* __restrict__ out, int n) {
    int i = blockIdx.x * blockDim.x + threadIdx.x;
    if (i < n) out[i] = 0.f;
}

// ---------------------------------------------------------------------------
// Kernel 4b: pooling, 4-way sequence split, half2 lanes, atomicMax combine
// ---------------------------------------------------------------------------
__global__ __launch_bounds__(128)
void pool_kernel(const int* __restrict__ text,
                 const float* __restrict__ b3,
                 const float* __restrict__ b4,
                 const float* __restrict__ b5,
                 float* __restrict__ out) {
    int blk = blockIdx.x;
    int seq = blk >> 2;
    int h   = blk & 3;
    int t0  = h * 32;
    int t1  = min(SEQL, t0 + 32 + 4);
    int n   = t1 - t0;
    int e3 = min(t0 + 32, SEQL - 2);
    int e4 = min(t0 + 32, SEQL - 3);
    int e5 = min(t0 + 32, SEQL - 4);

    __shared__ int s_tok[36];
    int ft = threadIdx.x;
    if (ft < n) s_tok[ft] = text[seq * SEQL + t0 + ft];
    __syncthreads();

    float2 m3 = make_float2(-1e30f, -1e30f), m4 = m3, m5 = m3;
    float2 z  = make_float2(0.f, 0.f);
    float2 c3a = z, c3b = z;
    float2 c4a = z, c4b = z, c4c = z;
    float2 c5a = z, c5b = z, c5c = z, c5d = z;

    for (int j = 0; j < n; j++) {
        const __half2* row =
            reinterpret_cast<const __half2*>(g_proj + (size_t)s_tok[j] * NCOL) + ft;
        float2 t0v  = __half22float2(row[0 * 128]);
        float2 t1v  = __half22float2(row[1 * 128]);
        float2 t2v  = __half22float2(row[2 * 128]);
        float2 t3v  = __half22float2(row[3 * 128]);
        float2 t4v  = __half22float2(row[4 * 128]);
        float2 t5v  = __half22float2(row[5 * 128]);
        float2 t6v  = __half22float2(row[6 * 128]);
        float2 t7v  = __half22float2(row[7 * 128]);
        float2 t8v  = __half22float2(row[8 * 128]);
        float2 t9v  = __half22float2(row[9 * 128]);
        float2 t10v = __half22float2(row[10 * 128]);
        float2 t11v = __half22float2(row[11 * 128]);

        int p = t0 + j;
        if (j >= 2 && (p - 2) < e3) m3 = max2(m3, add2(c3b, t2v));
        c3b = add2(c3a, t1v);  c3a = t0v;
        if (j >= 3 && (p - 3) < e4) m4 = max2(m4, add2(c4c, t6v));
        c4c = add2(c4b, t5v);  c4b = add2(c4a, t4v);  c4a = t3v;
        if (j >= 4 && (p - 4) < e5) m5 = max2(m5, add2(c5d, t11v));
        c5d = add2(c5c, t10v); c5c = add2(c5b, t9v);  c5b = add2(c5a, t8v);  c5a = t7v;
    }

    float2 bb3 = *reinterpret_cast<const float2*>(b3 + 2 * ft);
    float2 bb4 = *reinterpret_cast<const float2*>(b4 + 2 * ft);
    float2 bb5 = *reinterpret_cast<const float2*>(b5 + 2 * ft);

    unsigned int* o = reinterpret_cast<unsigned int*>(out + (size_t)seq * (3 * FEAT));
    atomicMax(&o[2 * ft],            __float_as_uint(fmaxf(m3.x + bb3.x, 0.f)));
    atomicMax(&o[2 * ft + 1],        __float_as_uint(fmaxf(m3.y + bb3.y, 0.f)));
    atomicMax(&o[FEAT + 2 * ft],     __float_as_uint(fmaxf(m4.x + bb4.x, 0.f)));
    atomicMax(&o[FEAT + 2 * ft + 1], __float_as_uint(fmaxf(m4.y + bb4.y, 0.f)));
    atomicMax(&o[2 * FEAT + 2 * ft],     __float_as_uint(fmaxf(m5.x + bb5.x, 0.f)));
    atomicMax(&o[2 * FEAT + 2 * ft + 1], __float_as_uint(fmaxf(m5.y + bb5.y, 0.f)));
}

// ---------------------------------------------------------------------------
extern "C" void kernel_launch(void* const* d_in, const int* in_sizes, int n_in,
                              void* d_out, int out_size) {
    const int*   text  = (const int*)  d_in[0];
    const float* embed = (const float*)d_in[1];
    const float* w3    = (const float*)d_in[2];
    const float* b3    = (const float*)d_in[3];
    const float* w4    = (const float*)d_in[4];
    const float* b4    = (const float*)d_in[5];
    const float* w5    = (const float*)d_in[6];
    const float* b5    = (const float*)d_in[7];
    float* out = (float*)d_out;

    convert_embed<<<(VOCAB * DIM / 8 + 255) / 256, 256>>>(embed);
    pack_w<<<(NCOL * DIM + 255) / 256, 256>>>(w3, w4, w5);
    init_out<<<(out_size + 1023) / 1024, 1024>>>(out, out_size);

    cudaFuncSetAttribute(gemm_f16, cudaFuncAttributeMaxDynamicSharedMemorySize, GEMM_SMEM);
    // 47 chains * 5 tiles = 235 m-tiles (covers 30080 >= 30000 rows)
    gemm_f16<<<dim3(NCOL / BN, 47), 256, GEMM_SMEM>>>();

    pool_kernel<<<NSEQ * 4, 128>>>(text, b3, b4, b5, out);
}

// round 9
// speedup vs baseline: 1.1348x; 1.1348x over previous
#include <cuda_runtime.h>
#include <cuda_fp16.h>
#include <stdint.h>

// ---------------------------------------------------------------------------
#define VOCAB 30000
#define DIM   512
#define FEAT  256
#define SEQL  128
#define NSEQ  1024
#define NCOL  3072

__device__ __align__(128) __half g_Ah[(size_t)VOCAB * DIM];
__device__ __align__(128) __half g_Bh[(size_t)NCOL * DIM];
__device__ __align__(128) __half g_proj[(size_t)VOCAB * NCOL];

// ---------------------------------------------------------------------------
static __device__ __forceinline__ uint32_t smem_u32(const void* p) {
    uint32_t a;
    asm("{ .reg .u64 t; cvta.to.shared.u64 t, %1; cvt.u32.u64 %0, t; }" : "=r"(a) : "l"(p));
    return a;
}
static __device__ __forceinline__ void cpa16(uint32_t s, const void* g) {
    asm volatile("cp.async.cg.shared.global [%0], [%1], 16;" :: "r"(s), "l"(g));
}
static __device__ __forceinline__ void cp_commit() {
    asm volatile("cp.async.commit_group;" ::: "memory");
}
template <int N> static __device__ __forceinline__ void cp_wait() {
    asm volatile("cp.async.wait_group %0;" :: "n"(N) : "memory");
}
static __device__ __forceinline__ void ldsm4(uint32_t& r0, uint32_t& r1,
                                             uint32_t& r2, uint32_t& r3, uint32_t a) {
    asm volatile("ldmatrix.sync.aligned.m8n8.x4.shared.b16 {%0,%1,%2,%3}, [%4];"
                 : "=r"(r0), "=r"(r1), "=r"(r2), "=r"(r3) : "r"(a));
}
static __device__ __forceinline__ void mma16816(float* d, const uint32_t* a,
                                                const uint32_t* b) {
    asm volatile(
        "mma.sync.aligned.m16n8k16.row.col.f32.f16.f16.f32 "
        "{%0,%1,%2,%3}, {%4,%5,%6,%7}, {%8,%9}, {%0,%1,%2,%3};"
        : "+f"(d[0]), "+f"(d[1]), "+f"(d[2]), "+f"(d[3])
        : "r"(a[0]), "r"(a[1]), "r"(a[2]), "r"(a[3]), "r"(b[0]), "r"(b[1]));
}
static __device__ __forceinline__ float2 add2(float2 a, float2 b) {
    return make_float2(a.x + b.x, a.y + b.y);
}
static __device__ __forceinline__ float2 max2(float2 a, float2 b) {
    return make_float2(fmaxf(a.x, b.x), fmaxf(a.y, b.y));
}

// ---------------------------------------------------------------------------
// Kernel 1: embed fp32 -> fp16
// ---------------------------------------------------------------------------
__global__ void convert_embed(const float* __restrict__ e) {
    size_t i = ((size_t)blockIdx.x * blockDim.x + threadIdx.x) * 8;
    if (i >= (size_t)VOCAB * DIM) return;
    float4 v0 = *reinterpret_cast<const float4*>(e + i);
    float4 v1 = *reinterpret_cast<const float4*>(e + i + 4);
    __align__(16) __half h[8];
    h[0] = __float2half_rn(v0.x); h[1] = __float2half_rn(v0.y);
    h[2] = __float2half_rn(v0.z); h[3] = __float2half_rn(v0.w);
    h[4] = __float2half_rn(v1.x); h[5] = __float2half_rn(v1.y);
    h[6] = __float2half_rn(v1.z); h[7] = __float2half_rn(v1.w);
    *reinterpret_cast<uint4*>(&g_Ah[i]) = *reinterpret_cast<uint4*>(h);
}

// ---------------------------------------------------------------------------
// Kernel 2: pack weights B[n][k], n = tap*256+f
// ---------------------------------------------------------------------------
__global__ void pack_w(const float* __restrict__ w3,
                       const float* __restrict__ w4,
                       const float* __restrict__ w5) {
    int idx = blockIdx.x * blockDim.x + threadIdx.x;
    if (idx >= NCOL * DIM) return;
    int n = idx >> 9;
    int k = idx & 511;
    int tap = n >> 8;
    int f   = n & 255;
    float v;
    if (tap < 3)      v = w3[(f * DIM + k) * 3 + tap];
    else if (tap < 7) v = w4[(f * DIM + k) * 4 + (tap - 3)];
    else              v = w5[(f * DIM + k) * 5 + (tap - 7)];
    g_Bh[idx] = __float2half_rn(v);
}

// ---------------------------------------------------------------------------
// Kernel 3: fp16 mma.sync GEMM, K=512
//   128x128 CTA tile, 4 warps (64x64 each), 3-stage cp.async pipeline,
//   2 CTAs per SM so pipeline bubbles of one CTA are covered by the other
// ---------------------------------------------------------------------------
#define BM 128
#define BN 128
#define BKH 64
#define STAGES 3
#define ASTG 16384                 // 128 rows * 128B
#define BSTG 16384
#define STG (ASTG + BSTG)          // 32KB / stage
#define NIT 8
#define GEMM_SMEM (STAGES * STG + 1024)

__global__ __launch_bounds__(128, 2) void gemm_f16() {
    extern __shared__ char dyn[];
    uint32_t base = (smem_u32(dyn) + 1023) & ~1023u;

    int tid  = threadIdx.x;
    int lane = tid & 31;
    int warp = tid >> 5;            // 0..3
    int wm = warp >> 1;             // 0..1
    int wn = warp & 1;              // 0..1
    int m0 = blockIdx.y * BM;
    int n0 = blockIdx.x * BN;

    int aRow[4], aXor[4];
#pragma unroll
    for (int mt = 0; mt < 4; mt++) {
        int r = wm * 64 + mt * 16 + (lane & 15);
        aRow[mt] = r * 128;
        aXor[mt] = r & 7;
    }
    int aCb = lane >> 4;
    int bRow[4], bXor[4];
#pragma unroll
    for (int ntp = 0; ntp < 4; ntp++) {
        int r = wn * 64 + ntp * 16 + (lane & 7) + ((lane >> 4) << 3);
        bRow[ntp] = r * 128;
        bXor[ntp] = r & 7;
    }
    int bCb = (lane >> 3) & 1;

    float acc[4][8][4];
#pragma unroll
    for (int mt = 0; mt < 4; mt++)
#pragma unroll
        for (int nt = 0; nt < 8; nt++)
#pragma unroll
            for (int q = 0; q < 4; q++) acc[mt][nt][q] = 0.f;

    auto load_stage = [&](int g) {
        int k0 = g * BKH;
        uint32_t sA = base + (g % STAGES) * STG;
        uint32_t sB = sA + ASTG;
#pragma unroll
        for (int j = 0; j < 8; j++) {              // A: 1024 chunks / 128 thr
            int c = tid + 128 * j;
            int r = c >> 3, q = c & 7;
            int grow = m0 + r; if (grow >= VOCAB) grow = VOCAB - 1;
            uint32_t off = (uint32_t)(r * 128 + ((q ^ (r & 7)) << 4));
            cpa16(sA + off, g_Ah + (size_t)grow * DIM + k0 + q * 8);
        }
#pragma unroll
        for (int j = 0; j < 8; j++) {              // B: 1024 chunks
            int c = tid + 128 * j;
            int r = c >> 3, q = c & 7;
            uint32_t off = (uint32_t)(r * 128 + ((q ^ (r & 7)) << 4));
            cpa16(sB + off, g_Bh + (size_t)(n0 + r) * DIM + k0 + q * 8);
        }
        cp_commit();
    };

    load_stage(0);
    load_stage(1);

    for (int i = 0; i < NIT; i++) {
        if (i == NIT - 1) cp_wait<0>(); else cp_wait<1>();
        __syncthreads();    // protects buffer (i+2)%3: reads of stage i-1 done

        if (i + 2 < NIT) load_stage(i + 2);

        uint32_t sA = base + (i % STAGES) * STG;
        uint32_t sB = sA + ASTG;

        uint32_t a[2][4][4], b[2][8][2];
        auto ldA = [&](int s, int buf) {
#pragma unroll
            for (int mt = 0; mt < 4; mt++) {
                uint32_t addr = sA + aRow[mt] + ((uint32_t)((2 * s + aCb) ^ aXor[mt]) << 4);
                ldsm4(a[buf][mt][0], a[buf][mt][1], a[buf][mt][2], a[buf][mt][3], addr);
            }
        };
        auto ldB = [&](int s, int buf) {
#pragma unroll
            for (int ntp = 0; ntp < 4; ntp++) {
                uint32_t addr = sB + bRow[ntp] + ((uint32_t)((2 * s + bCb) ^ bXor[ntp]) << 4);
                ldsm4(b[buf][2 * ntp][0], b[buf][2 * ntp][1],
                      b[buf][2 * ntp + 1][0], b[buf][2 * ntp + 1][1], addr);
            }
        };

        ldA(0, 0); ldB(0, 0);
#pragma unroll
        for (int s = 0; s < 4; s++) {
            int cur = s & 1;
            if (s < 3) { ldA(s + 1, cur ^ 1); ldB(s + 1, cur ^ 1); }
#pragma unroll
            for (int mt = 0; mt < 4; mt++)
#pragma unroll
                for (int nt = 0; nt < 8; nt++)
                    mma16816(acc[mt][nt], a[cur][mt], b[cur][nt]);
        }
    }

    // ---- epilogue: fp16 stores ----
#pragma unroll
    for (int mt = 0; mt < 4; mt++) {
        int r0 = m0 + wm * 64 + mt * 16 + (lane >> 2);
        int r1 = r0 + 8;
        __half* p0 = g_proj + (size_t)r0 * NCOL + n0 + wn * 64 + (lane & 3) * 2;
        __half* p1 = g_proj + (size_t)r1 * NCOL + n0 + wn * 64 + (lane & 3) * 2;
        bool ok0 = r0 < VOCAB, ok1 = r1 < VOCAB;
#pragma unroll
        for (int nt = 0; nt < 8; nt++) {
            if (ok0) *reinterpret_cast<__half2*>(p0 + nt * 8) =
                __floats2half2_rn(acc[mt][nt][0], acc[mt][nt][1]);
            if (ok1) *reinterpret_cast<__half2*>(p1 + nt * 8) =
                __floats2half2_rn(acc[mt][nt][2], acc[mt][nt][3]);
        }
    }
}

// ---------------------------------------------------------------------------
// Kernel 4a: zero output (atomicMax accumulation target)
// ---------------------------------------------------------------------------
__global__ void init_out(float* __restrict__ out, int n) {
    int i = blockIdx.x * blockDim.x + threadIdx.x;
    if (i < n) out[i] = 0.f;
}

// ---------------------------------------------------------------------------
// Kernel 4b: pooling, 4-way sequence split, half2 lanes, atomicMax combine
// ---------------------------------------------------------------------------
__global__ __launch_bounds__(128)
void pool_kernel(const int* __restrict__ text,
                 const float* __restrict__ b3,
                 const float* __restrict__ b4,
                 const float* __restrict__ b5,
                 float* __restrict__ out) {
    int blk = blockIdx.x;
    int seq = blk >> 2;
    int h   = blk & 3;
    int t0  = h * 32;
    int t1  = min(SEQL, t0 + 32 + 4);
    int n   = t1 - t0;
    int e3 = min(t0 + 32, SEQL - 2);
    int e4 = min(t0 + 32, SEQL - 3);
    int e5 = min(t0 + 32, SEQL - 4);

    __shared__ int s_tok[36];
    int ft = threadIdx.x;
    if (ft < n) s_tok[ft] = text[seq * SEQL + t0 + ft];
    __syncthreads();

    float2 m3 = make_float2(-1e30f, -1e30f), m4 = m3, m5 = m3;
    float2 z  = make_float2(0.f, 0.f);
    float2 c3a = z, c3b = z;
    float2 c4a = z, c4b = z, c4c = z;
    float2 c5a = z, c5b = z, c5c = z, c5d = z;

    for (int j = 0; j < n; j++) {
        const __half2* row =
            reinterpret_cast<const __half2*>(g_proj + (size_t)s_tok[j] * NCOL) + ft;
        float2 t0v  = __half22float2(row[0 * 128]);
        float2 t1v  = __half22float2(row[1 * 128]);
        float2 t2v  = __half22float2(row[2 * 128]);
        float2 t3v  = __half22float2(row[3 * 128]);
        float2 t4v  = __half22float2(row[4 * 128]);
        float2 t5v  = __half22float2(row[5 * 128]);
        float2 t6v  = __half22float2(row[6 * 128]);
        float2 t7v  = __half22float2(row[7 * 128]);
        float2 t8v  = __half22float2(row[8 * 128]);
        float2 t9v  = __half22float2(row[9 * 128]);
        float2 t10v = __half22float2(row[10 * 128]);
        float2 t11v = __half22float2(row[11 * 128]);

        int p = t0 + j;
        if (j >= 2 && (p - 2) < e3) m3 = max2(m3, add2(c3b, t2v));
        c3b = add2(c3a, t1v);  c3a = t0v;
        if (j >= 3 && (p - 3) < e4) m4 = max2(m4, add2(c4c, t6v));
        c4c = add2(c4b, t5v);  c4b = add2(c4a, t4v);  c4a = t3v;
        if (j >= 4 && (p - 4) < e5) m5 = max2(m5, add2(c5d, t11v));
        c5d = add2(c5c, t10v); c5c = add2(c5b, t9v);  c5b = add2(c5a, t8v);  c5a = t7v;
    }

    float2 bb3 = *reinterpret_cast<const float2*>(b3 + 2 * ft);
    float2 bb4 = *reinterpret_cast<const float2*>(b4 + 2 * ft);
    float2 bb5 = *reinterpret_cast<const float2*>(b5 + 2 * ft);

    unsigned int* o = reinterpret_cast<unsigned int*>(out + (size_t)seq * (3 * FEAT));
    atomicMax(&o[2 * ft],            __float_as_uint(fmaxf(m3.x + bb3.x, 0.f)));
    atomicMax(&o[2 * ft + 1],        __float_as_uint(fmaxf(m3.y + bb3.y, 0.f)));
    atomicMax(&o[FEAT + 2 * ft],     __float_as_uint(fmaxf(m4.x + bb4.x, 0.f)));
    atomicMax(&o[FEAT + 2 * ft + 1], __float_as_uint(fmaxf(m4.y + bb4.y, 0.f)));
    atomicMax(&o[2 * FEAT + 2 * ft],     __float_as_uint(fmaxf(m5.x + bb5.x, 0.f)));
    atomicMax(&o[2 * FEAT + 2 * ft + 1], __float_as_uint(fmaxf(m5.y + bb5.y, 0.f)));
}

// ---------------------------------------------------------------------------
extern "C" void kernel_launch(void* const* d_in, const int* in_sizes, int n_in,
                              void* d_out, int out_size) {
    const int*   text  = (const int*)  d_in[0];
    const float* embed = (const float*)d_in[1];
    const float* w3    = (const float*)d_in[2];
    const float* b3    = (const float*)d_in[3];
    const float* w4    = (const float*)d_in[4];
    const float* b4    = (const float*)d_in[5];
    const float* w5    = (const float*)d_in[6];
    const float* b5    = (const float*)d_in[7];
    float* out = (float*)d_out;

    convert_embed<<<(VOCAB * DIM / 8 + 255) / 256, 256>>>(embed);
    pack_w<<<(NCOL * DIM + 255) / 256, 256>>>(w3, w4, w5);
    init_out<<<(out_size + 1023) / 1024, 1024>>>(out, out_size);

    cudaFuncSetAttribute(gemm_f16, cudaFuncAttributeMaxDynamicSharedMemorySize, GEMM_SMEM);
    // 24 n-tiles x 235 m-tiles (covers 30080 >= 30000 rows)
    gemm_f16<<<dim3(NCOL / BN, 235), 128, GEMM_SMEM>>>();

    pool_kernel<<<NSEQ * 4, 128>>>(text, b3, b4, b5, out);
}

// round 10
// speedup vs baseline: 1.1618x; 1.0238x over previous
#include <cuda_runtime.h>
#include <cuda_fp16.h>
#include <stdint.h>

// ---------------------------------------------------------------------------
#define VOCAB 30000
#define DIM   512
#define FEAT  256
#define SEQL  128
#define NSEQ  1024
#define NCOL  3072

__device__ __align__(128) __half g_Ah[(size_t)VOCAB * DIM];
__device__ __align__(128) __half g_Bh[(size_t)NCOL * DIM];
__device__ __align__(128) __half g_proj[(size_t)VOCAB * NCOL];

// ---------------------------------------------------------------------------
static __device__ __forceinline__ uint32_t smem_u32(const void* p) {
    uint32_t a;
    asm("{ .reg .u64 t; cvta.to.shared.u64 t, %1; cvt.u32.u64 %0, t; }" : "=r"(a) : "l"(p));
    return a;
}
static __device__ __forceinline__ void cpa16(uint32_t s, const void* g) {
    asm volatile("cp.async.cg.shared.global [%0], [%1], 16;" :: "r"(s), "l"(g));
}
static __device__ __forceinline__ void cp_commit() {
    asm volatile("cp.async.commit_group;" ::: "memory");
}
template <int N> static __device__ __forceinline__ void cp_wait() {
    asm volatile("cp.async.wait_group %0;" :: "n"(N) : "memory");
}
static __device__ __forceinline__ void ldsm4(uint32_t& r0, uint32_t& r1,
                                             uint32_t& r2, uint32_t& r3, uint32_t a) {
    asm volatile("ldmatrix.sync.aligned.m8n8.x4.shared.b16 {%0,%1,%2,%3}, [%4];"
                 : "=r"(r0), "=r"(r1), "=r"(r2), "=r"(r3) : "r"(a));
}
static __device__ __forceinline__ void mma16816(float* d, const uint32_t* a,
                                                const uint32_t* b) {
    asm volatile(
        "mma.sync.aligned.m16n8k16.row.col.f32.f16.f16.f32 "
        "{%0,%1,%2,%3}, {%4,%5,%6,%7}, {%8,%9}, {%0,%1,%2,%3};"
        : "+f"(d[0]), "+f"(d[1]), "+f"(d[2]), "+f"(d[3])
        : "r"(a[0]), "r"(a[1]), "r"(a[2]), "r"(a[3]), "r"(b[0]), "r"(b[1]));
}
static __device__ __forceinline__ float2 add2(float2 a, float2 b) {
    return make_float2(a.x + b.x, a.y + b.y);
}
static __device__ __forceinline__ float2 max2(float2 a, float2 b) {
    return make_float2(fmaxf(a.x, b.x), fmaxf(a.y, b.y));
}

// ---------------------------------------------------------------------------
// Kernel 1 (merged prep): embed->fp16, pack weights, zero output
// ---------------------------------------------------------------------------
#define EMB_T  (VOCAB * DIM / 8)          // 1,920,000  (8 floats each)
#define PACK_T (NCOL * DIM)               // 1,572,864
#define INIT_T (NSEQ * 3 * FEAT / 4)      //   196,608  (float4 each)
#define PREP_T (EMB_T + PACK_T + INIT_T)

__global__ void prep(const float* __restrict__ e,
                     const float* __restrict__ w3,
                     const float* __restrict__ w4,
                     const float* __restrict__ w5,
                     float* __restrict__ out) {
    int idx = blockIdx.x * blockDim.x + threadIdx.x;
    if (idx < EMB_T) {
        size_t i = (size_t)idx * 8;
        float4 v0 = *reinterpret_cast<const float4*>(e + i);
        float4 v1 = *reinterpret_cast<const float4*>(e + i + 4);
        __align__(16) __half h[8];
        h[0] = __float2half_rn(v0.x); h[1] = __float2half_rn(v0.y);
        h[2] = __float2half_rn(v0.z); h[3] = __float2half_rn(v0.w);
        h[4] = __float2half_rn(v1.x); h[5] = __float2half_rn(v1.y);
        h[6] = __float2half_rn(v1.z); h[7] = __float2half_rn(v1.w);
        *reinterpret_cast<uint4*>(&g_Ah[i]) = *reinterpret_cast<uint4*>(h);
    } else if (idx < EMB_T + PACK_T) {
        int j = idx - EMB_T;
        int n = j >> 9;
        int k = j & 511;
        int tap = n >> 8;
        int f   = n & 255;
        float v;
        if (tap < 3)      v = w3[(f * DIM + k) * 3 + tap];
        else if (tap < 7) v = w4[(f * DIM + k) * 4 + (tap - 3)];
        else              v = w5[(f * DIM + k) * 5 + (tap - 7)];
        g_Bh[j] = __float2half_rn(v);
    } else if (idx < PREP_T) {
        int j = idx - EMB_T - PACK_T;
        *reinterpret_cast<float4*>(out + (size_t)j * 4) =
            make_float4(0.f, 0.f, 0.f, 0.f);
    }
}

// ---------------------------------------------------------------------------
// Kernel 2: fp16 mma.sync GEMM, K=512, 128x128 tile, 2 CTAs/SM,
//   cp.async issuance interleaved into the k-step loop
// ---------------------------------------------------------------------------
#define BM 128
#define BN 128
#define BKH 64
#define STAGES 3
#define ASTG 16384
#define BSTG 16384
#define STG (ASTG + BSTG)          // 32KB / stage
#define NIT 8
#define GEMM_SMEM (STAGES * STG + 1024)

__global__ __launch_bounds__(128, 2) void gemm_f16() {
    extern __shared__ char dyn[];
    uint32_t base = (smem_u32(dyn) + 1023) & ~1023u;

    int tid  = threadIdx.x;
    int lane = tid & 31;
    int warp = tid >> 5;
    int wm = warp >> 1;
    int wn = warp & 1;
    int m0 = blockIdx.y * BM;
    int n0 = blockIdx.x * BN;

    int aRow[4], aXor[4];
#pragma unroll
    for (int mt = 0; mt < 4; mt++) {
        int r = wm * 64 + mt * 16 + (lane & 15);
        aRow[mt] = r * 128;
        aXor[mt] = r & 7;
    }
    int aCb = lane >> 4;
    int bRow[4], bXor[4];
#pragma unroll
    for (int ntp = 0; ntp < 4; ntp++) {
        int r = wn * 64 + ntp * 16 + (lane & 7) + ((lane >> 4) << 3);
        bRow[ntp] = r * 128;
        bXor[ntp] = r & 7;
    }
    int bCb = (lane >> 3) & 1;

    float acc[4][8][4];
#pragma unroll
    for (int mt = 0; mt < 4; mt++)
#pragma unroll
        for (int nt = 0; nt < 8; nt++)
#pragma unroll
            for (int q = 0; q < 4; q++) acc[mt][nt][q] = 0.f;

    // full-stage load (prologue only)
    auto load_stage = [&](int g) {
        int k0 = g * BKH;
        uint32_t sA = base + (g % STAGES) * STG;
        uint32_t sB = sA + ASTG;
#pragma unroll
        for (int j = 0; j < 8; j++) {
            int c = tid + 128 * j;
            int r = c >> 3, q = c & 7;
            int grow = m0 + r; if (grow >= VOCAB) grow = VOCAB - 1;
            uint32_t off = (uint32_t)(r * 128 + ((q ^ (r & 7)) << 4));
            cpa16(sA + off, g_Ah + (size_t)grow * DIM + k0 + q * 8);
        }
#pragma unroll
        for (int j = 0; j < 8; j++) {
            int c = tid + 128 * j;
            int r = c >> 3, q = c & 7;
            uint32_t off = (uint32_t)(r * 128 + ((q ^ (r & 7)) << 4));
            cpa16(sB + off, g_Bh + (size_t)(n0 + r) * DIM + k0 + q * 8);
        }
        cp_commit();
    };
    // quarter-stage load (interleaved in mainloop; NO commit)
    auto load_quarter = [&](int g, int qq) {
        int k0 = g * BKH;
        uint32_t sA = base + (g % STAGES) * STG;
        uint32_t sB = sA + ASTG;
#pragma unroll
        for (int j = 2 * qq; j < 2 * qq + 2; j++) {
            int c = tid + 128 * j;
            int r = c >> 3, q = c & 7;
            int grow = m0 + r; if (grow >= VOCAB) grow = VOCAB - 1;
            uint32_t off = (uint32_t)(r * 128 + ((q ^ (r & 7)) << 4));
            cpa16(sA + off, g_Ah + (size_t)grow * DIM + k0 + q * 8);
        }
#pragma unroll
        for (int j = 2 * qq; j < 2 * qq + 2; j++) {
            int c = tid + 128 * j;
            int r = c >> 3, q = c & 7;
            uint32_t off = (uint32_t)(r * 128 + ((q ^ (r & 7)) << 4));
            cpa16(sB + off, g_Bh + (size_t)(n0 + r) * DIM + k0 + q * 8);
        }
    };

    load_stage(0);
    load_stage(1);

    for (int i = 0; i < NIT; i++) {
        if (i == NIT - 1) cp_wait<0>(); else cp_wait<1>();
        __syncthreads();

        uint32_t sA = base + (i % STAGES) * STG;
        uint32_t sB = sA + ASTG;
        bool pf = (i + 2 < NIT);

        uint32_t a[2][4][4], b[2][8][2];
        auto ldA = [&](int s, int buf) {
#pragma unroll
            for (int mt = 0; mt < 4; mt++) {
                uint32_t addr = sA + aRow[mt] + ((uint32_t)((2 * s + aCb) ^ aXor[mt]) << 4);
                ldsm4(a[buf][mt][0], a[buf][mt][1], a[buf][mt][2], a[buf][mt][3], addr);
            }
        };
        auto ldB = [&](int s, int buf) {
#pragma unroll
            for (int ntp = 0; ntp < 4; ntp++) {
                uint32_t addr = sB + bRow[ntp] + ((uint32_t)((2 * s + bCb) ^ bXor[ntp]) << 4);
                ldsm4(b[buf][2 * ntp][0], b[buf][2 * ntp][1],
                      b[buf][2 * ntp + 1][0], b[buf][2 * ntp + 1][1], addr);
            }
        };

        ldA(0, 0); ldB(0, 0);        // tensor restart path: ldsm first
#pragma unroll
        for (int s = 0; s < 4; s++) {
            int cur = s & 1;
            if (pf) load_quarter(i + 2, s);          // 4 cp.async, spread out
            if (s < 3) { ldA(s + 1, cur ^ 1); ldB(s + 1, cur ^ 1); }
#pragma unroll
            for (int mt = 0; mt < 4; mt++)
#pragma unroll
                for (int nt = 0; nt < 8; nt++)
                    mma16816(acc[mt][nt], a[cur][mt], b[cur][nt]);
        }
        if (pf) cp_commit();
    }

    // ---- epilogue: fp16 stores ----
#pragma unroll
    for (int mt = 0; mt < 4; mt++) {
        int r0 = m0 + wm * 64 + mt * 16 + (lane >> 2);
        int r1 = r0 + 8;
        __half* p0 = g_proj + (size_t)r0 * NCOL + n0 + wn * 64 + (lane & 3) * 2;
        __half* p1 = g_proj + (size_t)r1 * NCOL + n0 + wn * 64 + (lane & 3) * 2;
        bool ok0 = r0 < VOCAB, ok1 = r1 < VOCAB;
#pragma unroll
        for (int nt = 0; nt < 8; nt++) {
            if (ok0) *reinterpret_cast<__half2*>(p0 + nt * 8) =
                __floats2half2_rn(acc[mt][nt][0], acc[mt][nt][1]);
            if (ok1) *reinterpret_cast<__half2*>(p1 + nt * 8) =
                __floats2half2_rn(acc[mt][nt][2], acc[mt][nt][3]);
        }
    }
}

// ---------------------------------------------------------------------------
// Kernel 3: pooling, 4-way sequence split, half2 lanes, atomicMax combine
// ---------------------------------------------------------------------------
__global__ __launch_bounds__(128)
void pool_kernel(const int* __restrict__ text,
                 const float* __restrict__ b3,
                 const float* __restrict__ b4,
                 const float* __restrict__ b5,
                 float* __restrict__ out) {
    int blk = blockIdx.x;
    int seq = blk >> 2;
    int h   = blk & 3;
    int t0  = h * 32;
    int t1  = min(SEQL, t0 + 32 + 4);
    int n   = t1 - t0;
    int e3 = min(t0 + 32, SEQL - 2);
    int e4 = min(t0 + 32, SEQL - 3);
    int e5 = min(t0 + 32, SEQL - 4);

    __shared__ int s_tok[36];
    int ft = threadIdx.x;
    if (ft < n) s_tok[ft] = text[seq * SEQL + t0 + ft];
    __syncthreads();

    float2 m3 = make_float2(-1e30f, -1e30f), m4 = m3, m5 = m3;
    float2 z  = make_float2(0.f, 0.f);
    float2 c3a = z, c3b = z;
    float2 c4a = z, c4b = z, c4c = z;
    float2 c5a = z, c5b = z, c5c = z, c5d = z;

    for (int j = 0; j < n; j++) {
        const __half2* row =
            reinterpret_cast<const __half2*>(g_proj + (size_t)s_tok[j] * NCOL) + ft;
        float2 t0v  = __half22float2(row[0 * 128]);
        float2 t1v  = __half22float2(row[1 * 128]);
        float2 t2v  = __half22float2(row[2 * 128]);
        float2 t3v  = __half22float2(row[3 * 128]);
        float2 t4v  = __half22float2(row[4 * 128]);
        float2 t5v  = __half22float2(row[5 * 128]);
        float2 t6v  = __half22float2(row[6 * 128]);
        float2 t7v  = __half22float2(row[7 * 128]);
        float2 t8v  = __half22float2(row[8 * 128]);
        float2 t9v  = __half22float2(row[9 * 128]);
        float2 t10v = __half22float2(row[10 * 128]);
        float2 t11v = __half22float2(row[11 * 128]);

        int p = t0 + j;
        if (j >= 2 && (p - 2) < e3) m3 = max2(m3, add2(c3b, t2v));
        c3b = add2(c3a, t1v);  c3a = t0v;
        if (j >= 3 && (p - 3) < e4) m4 = max2(m4, add2(c4c, t6v));
        c4c = add2(c4b, t5v);  c4b = add2(c4a, t4v);  c4a = t3v;
        if (j >= 4 && (p - 4) < e5) m5 = max2(m5, add2(c5d, t11v));
        c5d = add2(c5c, t10v); c5c = add2(c5b, t9v);  c5b = add2(c5a, t8v);  c5a = t7v;
    }

    float2 bb3 = *reinterpret_cast<const float2*>(b3 + 2 * ft);
    float2 bb4 = *reinterpret_cast<const float2*>(b4 + 2 * ft);
    float2 bb5 = *reinterpret_cast<const float2*>(b5 + 2 * ft);

    unsigned int* o = reinterpret_cast<unsigned int*>(out + (size_t)seq * (3 * FEAT));
    atomicMax(&o[2 * ft],            __float_as_uint(fmaxf(m3.x + bb3.x, 0.f)));
    atomicMax(&o[2 * ft + 1],        __float_as_uint(fmaxf(m3.y + bb3.y, 0.f)));
    atomicMax(&o[FEAT + 2 * ft],     __float_as_uint(fmaxf(m4.x + bb4.x, 0.f)));
    atomicMax(&o[FEAT + 2 * ft + 1], __float_as_uint(fmaxf(m4.y + bb4.y, 0.f)));
    atomicMax(&o[2 * FEAT + 2 * ft],     __float_as_uint(fmaxf(m5.x + bb5.x, 0.f)));
    atomicMax(&o[2 * FEAT + 2 * ft + 1], __float_as_uint(fmaxf(m5.y + bb5.y, 0.f)));
}

// ---------------------------------------------------------------------------
extern "C" void kernel_launch(void* const* d_in, const int* in_sizes, int n_in,
                              void* d_out, int out_size) {
    const int*   text  = (const int*)  d_in[0];
    const float* embed = (const float*)d_in[1];
    const float* w3    = (const float*)d_in[2];
    const float* b3    = (const float*)d_in[3];
    const float* w4    = (const float*)d_in[4];
    const float* b4    = (const float*)d_in[5];
    const float* w5    = (const float*)d_in[6];
    const float* b5    = (const float*)d_in[7];
    float* out = (float*)d_out;

    prep<<<(PREP_T + 255) / 256, 256>>>(embed, w3, w4, w5, out);

    cudaFuncSetAttribute(gemm_f16, cudaFuncAttributeMaxDynamicSharedMemorySize, GEMM_SMEM);
    gemm_f16<<<dim3(NCOL / BN, 235), 128, GEMM_SMEM>>>();

    pool_kernel<<<NSEQ * 4, 128>>>(text, b3, b4, b5, out);
}